// round 2
// baseline (speedup 1.0000x reference)
#include <cuda_runtime.h>
#include <cuda_bf16.h>
#include <math_constants.h>

#define FEAT 50
#define NPOS 2500
#define NA 9
#define NBOX 22500
#define CIN 2048
#define CMID 1024
#define KJ (CIN*9)        // 18432
#define NOUT 45
#define NSPLIT 16
#define PRE 6000
#define POST 300
#define NW 188            // ceil(6000/32)
#define NBIN 65536

// ------------------ scratch (no allocations allowed) ------------------
__device__ float      g_Weff[KJ * NOUT];            // [j][45], j = c'*9 + ky*3 + kx
__device__ float      g_bias[NOUT];
__device__ float      g_Psplit[NSPLIT * NPOS * NOUT];
__device__ float4     g_roi[NBOX];
__device__ uint2      g_key[NBOX];                  // (hi = desc score bits, lo = index)
__device__ unsigned   g_hist[NBIN];
__device__ unsigned   g_cutoff;
__device__ int        g_subCnt;
__device__ uint2      g_subKey[NBOX];
__device__ float4     g_sbox[PRE];
__device__ unsigned   g_validBits[NW];
__device__ unsigned   g_mask[(size_t)PRE * NW];

// ------------------ zero scratch ------------------
__global__ void zero_kernel() {
    int i = blockIdx.x * 256 + threadIdx.x;
    if (i < NBIN) g_hist[i] = 0u;
    if (i < NW)   g_validBits[i] = 0u;
    if (i == 0)   g_subCnt = 0;
}

// ------------------ fold: Weff = Whead @ W1 ------------------
// grid (72, 3): 72 j-blocks of 256 columns, 3 groups of 15 outputs. 128 threads.
__global__ __launch_bounds__(128) void fold_kernel(
    const float* __restrict__ W1, const float* __restrict__ Wreg,
    const float* __restrict__ Wcls)
{
    const int t  = threadIdx.x;
    const int j0 = blockIdx.x * 256;
    const int ag = blockIdx.y;            // output group: rows ag*15 .. ag*15+14

    __shared__ float sW1[32][256];
    __shared__ float sH[15][33];

    float tot0[15], tot1[15], cmp0[15], cmp1[15];
#pragma unroll
    for (int s = 0; s < 15; s++) { tot0[s]=tot1[s]=cmp0[s]=cmp1[s]=0.f; }

    for (int ct = 0; ct < CMID / 32; ct++) {
        // load W1 tile [32 x 256], coalesced
        for (int idx = t; idx < 32 * 256; idx += 128) {
            int r = idx >> 8, col = idx & 255;
            sW1[r][col] = W1[(size_t)(ct * 32 + r) * KJ + j0 + col];
        }
        // load head rows [15 x 32]
        for (int idx = t; idx < 15 * 32; idx += 128) {
            int s = idx >> 5, c = idx & 31;
            int sg = ag * 15 + s;
            int k  = ct * 32 + c;
            float h = (sg < 36) ? Wreg[sg * CMID + k]
                                : Wcls[(2 * (sg - 36) + 1) * CMID + k];
            sH[s][c] = h;
        }
        __syncthreads();

        float a0[15], a1[15];
#pragma unroll
        for (int s = 0; s < 15; s++) { a0[s]=0.f; a1[s]=0.f; }
#pragma unroll 4
        for (int c = 0; c < 32; c++) {
            float b0 = sW1[c][t];
            float b1 = sW1[c][t + 128];
#pragma unroll
            for (int s = 0; s < 15; s++) {
                float h = sH[s][c];
                a0[s] = fmaf(h, b0, a0[s]);
                a1[s] = fmaf(h, b1, a1[s]);
            }
        }
        // Kahan-add tile sums into totals (keeps Weff error ~3e-7 rel)
#pragma unroll
        for (int s = 0; s < 15; s++) {
            float y0 = a0[s] - cmp0[s];
            float t0 = tot0[s] + y0;
            cmp0[s] = (t0 - tot0[s]) - y0;
            tot0[s] = t0;
            float y1 = a1[s] - cmp1[s];
            float t1 = tot1[s] + y1;
            cmp1[s] = (t1 - tot1[s]) - y1;
            tot1[s] = t1;
        }
        __syncthreads();
    }
#pragma unroll
    for (int s = 0; s < 15; s++) {
        g_Weff[(size_t)(j0 + t)       * NOUT + ag * 15 + s] = tot0[s];
        g_Weff[(size_t)(j0 + t + 128) * NOUT + ag * 15 + s] = tot1[s];
    }
}

// ------------------ effective biases (b1 folded through heads) ------------------
__global__ void bias_kernel(const float* __restrict__ Wreg, const float* __restrict__ breg,
                            const float* __restrict__ Wcls, const float* __restrict__ bcls,
                            const float* __restrict__ b1)
{
    int s = threadIdx.x;
    if (s >= NOUT) return;
    const float* row;
    float hb;
    if (s < 36) { row = Wreg + s * CMID; hb = breg[s]; }
    else        { int a = s - 36; row = Wcls + (2 * a + 1) * CMID; hb = bcls[2 * a + 1]; }
    float acc = 0.f;
    for (int k = 0; k < CMID; k++) acc = fmaf(row[k], b1[k], acc);
    g_bias[s] = hb + acc;
}

// ------------------ main folded conv: P[p][45], C-split partials ------------------
// grid (NSPLIT=16, 10 y-groups), 450 threads: (a-group 9) x (x-group 10) x (y-sub 5)
__global__ __launch_bounds__(450) void main_kernel(const float* __restrict__ feat)
{
    const int t  = threadIdx.x;
    const int ag = t % 9;
    const int xg = (t / 9) % 10;
    const int ys = t / 90;
    const int cs = blockIdx.x;
    const int yg = blockIdx.y;

    const int y  = yg * 5 + ys;
    const int xb = xg * 5;

    __shared__ float sF[8 * 7 * 52];   // [cc][r][col], col = gx+1
    __shared__ float sW[8 * 9 * 45];   // [cc][k9][a]

    float tot[5][5];
#pragma unroll
    for (int i = 0; i < 5; i++)
#pragma unroll
        for (int m = 0; m < 5; m++) tot[i][m] = 0.f;

    for (int ct = 0; ct < 16; ct++) {
        const int c0 = cs * 128 + ct * 8;
        // features tile: 8 ch x 7 rows x 52 cols (with zero halo)
        for (int idx = t; idx < 8 * 7 * 52; idx += 450) {
            int cc  = idx / 364;
            int rem = idx - cc * 364;
            int r   = rem / 52, col = rem - r * 52;
            int gy  = yg * 5 - 1 + r;
            int gx  = col - 1;
            float v = 0.f;
            if (gy >= 0 && gy < FEAT && gx >= 0 && gx < FEAT)
                v = feat[(size_t)(c0 + cc) * NPOS + gy * FEAT + gx];
            sF[idx] = v;
        }
        // Weff tile: contiguous 8*9*45 chunk
        for (int idx = t; idx < 8 * 9 * 45; idx += 450)
            sW[idx] = g_Weff[(size_t)c0 * 9 * NOUT + idx];
        __syncthreads();

        float acc[5][5];
#pragma unroll
        for (int i = 0; i < 5; i++)
#pragma unroll
            for (int m = 0; m < 5; m++) acc[i][m] = 0.f;

        for (int cc = 0; cc < 8; cc++) {
#pragma unroll
            for (int ky = 0; ky < 3; ky++) {
                const float* fr = &sF[cc * 364 + (ys + ky) * 52 + xb];
                float fv[7];
#pragma unroll
                for (int q = 0; q < 7; q++) fv[q] = fr[q];
                const float* wr = &sW[(cc * 9 + ky * 3) * NOUT];
#pragma unroll
                for (int i = 0; i < 5; i++) {
                    int a = ag * 5 + i;
                    float w0 = wr[a], w1 = wr[NOUT + a], w2 = wr[2 * NOUT + a];
#pragma unroll
                    for (int m = 0; m < 5; m++)
                        acc[i][m] = fmaf(w0, fv[m],
                                    fmaf(w1, fv[m + 1],
                                    fmaf(w2, fv[m + 2], acc[i][m])));
                }
            }
        }
#pragma unroll
        for (int i = 0; i < 5; i++)
#pragma unroll
            for (int m = 0; m < 5; m++) tot[i][m] += acc[i][m];
        __syncthreads();
    }

#pragma unroll
    for (int i = 0; i < 5; i++)
#pragma unroll
        for (int m = 0; m < 5; m++)
            g_Psplit[(size_t)cs * (NPOS * NOUT) + (y * FEAT + xb + m) * NOUT + ag * 5 + i]
                = tot[i][m];
}

// ------------------ reduce + decode + key + histogram ------------------
__global__ void decode_kernel(const float* __restrict__ anchors)
{
    int i = blockIdx.x * 256 + threadIdx.x;
    if (i >= NBOX) return;
    int p = i / 9, a = i - p * 9;

    float v[5];
#pragma unroll
    for (int d = 0; d < 5; d++) {
        int ch = (d < 4) ? (a * 4 + d) : (36 + a);
        float s = g_bias[ch];
#pragma unroll
        for (int sp = 0; sp < NSPLIT; sp++)
            s += g_Psplit[(size_t)sp * (NPOS * NOUT) + p * NOUT + ch];
        v[d] = s;
    }

    float ay1 = anchors[i * 4 + 0], ax1 = anchors[i * 4 + 1];
    float ay2 = anchors[i * 4 + 2], ax2 = anchors[i * 4 + 3];
    float ah = ay2 - ay1, aw = ax2 - ax1;
    float acy = ay1 + 0.5f * ah, acx = ax1 + 0.5f * aw;
    float cy = v[0] * ah + acy, cx = v[1] * aw + acx;
    float h  = expf(v[2]) * ah, w  = expf(v[3]) * aw;

    float r0 = fminf(fmaxf(cy - 0.5f * h, 0.f), 800.f);
    float r1 = fminf(fmaxf(cx - 0.5f * w, 0.f), 800.f);
    float r2 = fminf(fmaxf(cy + 0.5f * h, 0.f), 800.f);
    float r3 = fminf(fmaxf(cx + 0.5f * w, 0.f), 800.f);

    bool valid = ((r2 - r0) >= 16.f) && ((r3 - r1) >= 16.f);
    float score = valid ? v[4] : -CUDART_INF_F;

    g_roi[i] = make_float4(r0, r1, r2, r3);

    unsigned f   = __float_as_uint(score);
    unsigned asc = f ^ ((f >> 31) ? 0xFFFFFFFFu : 0x80000000u); // ascending-sortable
    unsigned hi  = ~asc;                                        // ascending == descending score
    g_key[i] = make_uint2(hi, (unsigned)i);
    atomicAdd(&g_hist[hi >> 16], 1u);
}

// ------------------ find cutoff bin so suffix count >= PRE ------------------
__global__ void binscan_kernel()
{
    __shared__ unsigned s[256];
    int t = threadIdx.x;
    unsigned sum = 0;
    for (int b = 0; b < 256; b++) sum += g_hist[t * 256 + b];
    s[t] = sum;
    __syncthreads();
    if (t == 0) {
        unsigned cum = 0;
        int cutoff = NBIN - 1;
        for (int g = 0; g < 256; g++) {
            if (cum + s[g] >= (unsigned)PRE) {
                unsigned target = (unsigned)PRE - cum;
                unsigned c2 = 0;
                for (int b = 0; b < 256; b++) {
                    c2 += g_hist[g * 256 + b];
                    if (c2 >= target) { cutoff = g * 256 + b; break; }
                }
                break;
            }
            cum += s[g];
        }
        g_cutoff = (unsigned)cutoff;
    }
}

// ------------------ compact candidate subset ------------------
__global__ void subsel_kernel()
{
    int i = blockIdx.x * 256 + threadIdx.x;
    if (i >= NBOX) return;
    uint2 k = g_key[i];
    if ((k.x >> 16) <= g_cutoff) {
        int pos = atomicAdd(&g_subCnt, 1);
        g_subKey[pos] = k;
    }
}

// ------------------ exact rank of subset, scatter top-6000 ------------------
__global__ void rank_kernel()
{
    const int e = blockIdx.x * 256 + threadIdx.x;
    const int C = g_subCnt;
    uint2 my = (e < C) ? g_subKey[e] : make_uint2(0u, 0u);
    unsigned rank = 0;
    __shared__ uint2 tile[256];
    for (int t0 = 0; t0 < C; t0 += 256) {
        int idx = t0 + threadIdx.x;
        tile[threadIdx.x] = (idx < C) ? g_subKey[idx]
                                      : make_uint2(0xFFFFFFFFu, 0xFFFFFFFFu);
        __syncthreads();
        int lim = min(256, C - t0);
        if (e < C) {
            for (int q = 0; q < lim; q++) {
                uint2 k = tile[q];
                rank += (k.x < my.x) || (k.x == my.x && k.y < my.y);
            }
        }
        __syncthreads();
    }
    if (e < C && rank < (unsigned)PRE) {
        g_sbox[rank] = g_roi[my.y];
        if (my.x < 0xFF800000u)   // score > -inf
            atomicOr(&g_validBits[rank >> 5], 1u << (rank & 31));
    }
}

// ------------------ suppression bitmask: mask[i][jword] (j > i, iou > 0.7) ------------------
__global__ void mask_kernel()
{
    const int it = blockIdx.x, jt = blockIdx.y;
    const int i = it * 32 + threadIdx.x;
    __shared__ float4 jb[32];
    int j0 = jt * 32;
    int jj = j0 + threadIdx.x;
    jb[threadIdx.x] = (jj < PRE) ? g_sbox[jj] : make_float4(0.f, 0.f, 0.f, 0.f);
    __syncwarp();
    if (i >= PRE) return;
    float4 bi = g_sbox[i];
    float areai = (bi.w - bi.y + 1.f) * (bi.z - bi.x + 1.f);
    unsigned word = 0u;
#pragma unroll 8
    for (int q = 0; q < 32; q++) {
        int j = j0 + q;
        if (j > i && j < PRE) {
            float4 bj = jb[q];
            float yy1 = fmaxf(bi.x, bj.x), xx1 = fmaxf(bi.y, bj.y);
            float yy2 = fminf(bi.z, bj.z), xx2 = fminf(bi.w, bj.w);
            float inter = fmaxf(0.f, xx2 - xx1 + 1.f) * fmaxf(0.f, yy2 - yy1 + 1.f);
            float areaj = (bj.w - bj.y + 1.f) * (bj.z - bj.x + 1.f);
            float iou = inter / (areai + areaj - inter);
            if (iou > 0.7f) word |= (1u << q);
        }
    }
    g_mask[(size_t)i * NW + jt] = word;
}

// ------------------ serial greedy NMS (one warp) ------------------
__global__ void nms_kernel(float* __restrict__ out)
{
    const int lane = threadIdx.x;
    __shared__ unsigned rem[NW], val[NW];
    for (int w = lane; w < NW; w += 32) { rem[w] = 0u; val[w] = g_validBits[w]; }
    for (int k = lane; k < POST * 4; k += 32) out[k] = 0.f;
    __syncwarp();

    int kept = 0;
    for (int w = 0; w < NW && kept < POST; w++) {
        while (kept < POST) {
            unsigned avail = val[w] & ~rem[w];
            if (!avail) break;
            int b = __ffs(avail) - 1;
            int i = w * 32 + b;
            if (lane == 0) {
                float4 bx = g_sbox[i];
                out[kept * 4 + 0] = bx.x;
                out[kept * 4 + 1] = bx.y;
                out[kept * 4 + 2] = bx.z;
                out[kept * 4 + 3] = bx.w;
                rem[w] |= (1u << b);
            }
            __syncwarp();
            const unsigned* mr = &g_mask[(size_t)i * NW];
            for (int w2 = lane; w2 < NW; w2 += 32) rem[w2] |= mr[w2];
            __syncwarp();
            kept++;
        }
    }
}

// ------------------ launch ------------------
extern "C" void kernel_launch(void* const* d_in, const int* in_sizes, int n_in,
                              void* d_out, int out_size)
{
    const float* feat    = (const float*)d_in[0];
    const float* anchors = (const float*)d_in[1];
    const float* W1      = (const float*)d_in[2];
    const float* b1      = (const float*)d_in[3];
    const float* Wreg    = (const float*)d_in[4];
    const float* breg    = (const float*)d_in[5];
    const float* Wcls    = (const float*)d_in[6];
    const float* bcls    = (const float*)d_in[7];
    float* out = (float*)d_out;

    zero_kernel<<<(NBIN + 255) / 256, 256>>>();
    fold_kernel<<<dim3(KJ / 256, 3), 128>>>(W1, Wreg, Wcls);
    bias_kernel<<<1, 64>>>(Wreg, breg, Wcls, bcls, b1);
    main_kernel<<<dim3(NSPLIT, 10), 450>>>(feat);
    decode_kernel<<<(NBOX + 255) / 256, 256>>>(anchors);
    binscan_kernel<<<1, 256>>>();
    subsel_kernel<<<(NBOX + 255) / 256, 256>>>();
    rank_kernel<<<(NBOX + 255) / 256, 256>>>();
    mask_kernel<<<dim3(NW, NW), 32>>>();
    nms_kernel<<<1, 32>>>(out);
}

// round 3
// speedup vs baseline: 1.7268x; 1.7268x over previous
#include <cuda_runtime.h>
#include <cuda_bf16.h>
#include <math_constants.h>

#define FEAT 50
#define NPOS 2500
#define NA 9
#define NBOX 22500
#define CIN 2048
#define CMID 1024
#define KJ (CIN*9)        // 18432
#define NOUT 45
#define NSPLIT 16
#define PRE 6000
#define POST 300
#define NW 188            // ceil(6000/32)
#define NBIN 65536

typedef unsigned long long ull;

// ---------- packed fp32x2 helpers (Blackwell FFMA2 path) ----------
__device__ __forceinline__ ull pack2(float lo, float hi) {
    ull d; asm("mov.b64 %0, {%1, %2};" : "=l"(d) : "f"(lo), "f"(hi)); return d;
}
__device__ __forceinline__ void unpack2(ull p, float& lo, float& hi) {
    asm("mov.b64 {%0, %1}, %2;" : "=f"(lo), "=f"(hi) : "l"(p));
}
__device__ __forceinline__ ull ffma2(ull a, ull b, ull c) {
    ull d; asm("fma.rn.f32x2 %0, %1, %2, %3;" : "=l"(d) : "l"(a), "l"(b), "l"(c)); return d;
}
__device__ __forceinline__ ull fadd2(ull a, ull b) {
    ull d; asm("add.rn.f32x2 %0, %1, %2;" : "=l"(d) : "l"(a), "l"(b)); return d;
}

// ------------------ scratch ------------------
__device__ float      g_Weff[KJ * NOUT];            // [j][45], j = c'*9 + ky*3 + kx
__device__ float      g_bias[NOUT];
__device__ float      g_Psplit[NSPLIT * NPOS * NOUT];
__device__ float4     g_roi[NBOX];
__device__ uint2      g_key[NBOX];
__device__ unsigned   g_hist[NBIN];
__device__ unsigned   g_cutoff;
__device__ int        g_subCnt;
__device__ uint2      g_subKey[NBOX];
__device__ float4     g_sbox[PRE];
__device__ unsigned   g_validBits[NW];
__device__ unsigned   g_mask[(size_t)PRE * NW];

// ------------------ zero scratch ------------------
__global__ void zero_kernel() {
    int i = blockIdx.x * 256 + threadIdx.x;
    if (i < NBIN) g_hist[i] = 0u;
    if (i < NW)   g_validBits[i] = 0u;
    if (i == 0)   g_subCnt = 0;
}

// ------------------ fold: Weff = Whead @ W1 ------------------
// grid 144: 144 j-blocks of 128 cols. block 192 = 3 out-groups x 64 threads.
// Thread owns adjacent column pair (j0+2tt, j0+2tt+1) -> packed FFMA2.
__global__ __launch_bounds__(192) void fold_kernel(
    const float* __restrict__ W1, const float* __restrict__ Wreg,
    const float* __restrict__ Wcls)
{
    const int t  = threadIdx.x;
    const int g  = t >> 6;          // 0..2 output group
    const int tt = t & 63;          // column-pair index
    const int j0 = blockIdx.x * 128;

    __shared__ ull sB[32][64];      // W1 tile as column pairs [k-row][pair]
    __shared__ ull sH2[45][33];     // head weights duplicated (h,h), padded

    ull tP[15];
#pragma unroll
    for (int s = 0; s < 15; s++) tP[s] = 0ULL;

    for (int ct = 0; ct < 32; ct++) {
        // stage W1 tile: 32 rows x 64 pairs, coalesced float2 loads
        for (int idx = t; idx < 32 * 64; idx += 192) {
            int r = idx >> 6, q = idx & 63;
            const float2 v = *(const float2*)&W1[(size_t)(ct * 32 + r) * KJ + j0 + 2 * q];
            sB[r][q] = pack2(v.x, v.y);
        }
        // stage head rows duplicated
        for (int idx = t; idx < 45 * 32; idx += 192) {
            int s = idx >> 5, c = idx & 31;
            int k = ct * 32 + c;
            float h = (s < 36) ? Wreg[s * CMID + k]
                               : Wcls[(2 * (s - 36) + 1) * CMID + k];
            sH2[s][c] = pack2(h, h);
        }
        __syncthreads();

        ull aP[15];
#pragma unroll
        for (int s = 0; s < 15; s++) aP[s] = 0ULL;
#pragma unroll 4
        for (int c = 0; c < 32; c++) {
            ull B = sB[c][tt];
#pragma unroll
            for (int s = 0; s < 15; s++)
                aP[s] = ffma2(sH2[g * 15 + s][c], B, aP[s]);
        }
#pragma unroll
        for (int s = 0; s < 15; s++) tP[s] = fadd2(tP[s], aP[s]);
        __syncthreads();
    }

    const int jA = j0 + 2 * tt;
#pragma unroll
    for (int s = 0; s < 15; s++) {
        float lo, hi; unpack2(tP[s], lo, hi);
        g_Weff[(size_t)jA * NOUT + g * 15 + s]       = lo;
        g_Weff[(size_t)(jA + 1) * NOUT + g * 15 + s] = hi;
    }
}

// ------------------ effective biases ------------------
__global__ void bias_kernel(const float* __restrict__ Wreg, const float* __restrict__ breg,
                            const float* __restrict__ Wcls, const float* __restrict__ bcls,
                            const float* __restrict__ b1)
{
    int s = threadIdx.x;
    if (s >= NOUT) return;
    const float* row;
    float hb;
    if (s < 36) { row = Wreg + s * CMID; hb = breg[s]; }
    else        { int a = s - 36; row = Wcls + (2 * a + 1) * CMID; hb = bcls[2 * a + 1]; }
    float acc = 0.f;
    for (int k = 0; k < CMID; k++) acc = fmaf(row[k], b1[k], acc);
    g_bias[s] = hb + acc;
}

// ------------------ main folded conv (packed FFMA2) ------------------
// grid (16 csplit, 25 y-pairs) = 400 blocks, 192 threads (180 active:
// ag(9) x xg(10) x ys(2)). Thread tile: 5 outs x 5 x-cols (2 packed + 1 scalar).
__global__ __launch_bounds__(192, 5) void main_kernel(const float* __restrict__ feat)
{
    const int t  = threadIdx.x;
    const int cs = blockIdx.x;
    const int yg = blockIdx.y;

    const int ag = t % 9;
    const int xg = (t / 9) % 10;
    const int ys = t / 90;           // 0..1 (t<180)
    const bool act = (t < 180);
    const int y  = yg * 2 + ys;
    const int xb = xg * 5;

    __shared__ float sF[8 * 4 * 52];   // [cc][r(4)][col(52)] with halo
    __shared__ ull   sWu[8 * 9 * 45];  // weights duplicated (w,w)

    ull   A0[5], A1[5];
    float s4[5];
#pragma unroll
    for (int i = 0; i < 5; i++) { A0[i] = 0ULL; A1[i] = 0ULL; s4[i] = 0.f; }

    for (int ct = 0; ct < 16; ct++) {
        const int c0 = cs * 128 + ct * 8;
        for (int idx = t; idx < 8 * 4 * 52; idx += 192) {
            int cc  = idx / 208;
            int rem = idx - cc * 208;
            int r   = rem / 52, col = rem - r * 52;
            int gy  = yg * 2 - 1 + r;
            int gx  = col - 1;
            float v = 0.f;
            if (gy >= 0 && gy < FEAT && gx >= 0 && gx < FEAT)
                v = feat[(size_t)(c0 + cc) * NPOS + gy * FEAT + gx];
            sF[idx] = v;
        }
        for (int idx = t; idx < 8 * 9 * 45; idx += 192) {
            float w = g_Weff[(size_t)c0 * 9 * NOUT + idx];
            sWu[idx] = pack2(w, w);
        }
        __syncthreads();

        if (act) {
            for (int cc = 0; cc < 8; cc++) {
#pragma unroll
                for (int ky = 0; ky < 3; ky++) {
                    const float* fr = &sF[cc * 208 + (ys + ky) * 52 + xb];
                    float f0 = fr[0], f1 = fr[1], f2 = fr[2], f3 = fr[3];
                    float f4 = fr[4], f5 = fr[5], f6 = fr[6];
                    ull P01 = pack2(f0, f1), P12 = pack2(f1, f2);
                    ull P23 = pack2(f2, f3), P34 = pack2(f3, f4);
                    ull P45 = pack2(f4, f5);
                    const ull* wr = &sWu[(cc * 9 + ky * 3) * NOUT];
#pragma unroll
                    for (int i = 0; i < 5; i++) {
                        int a = ag * 5 + i;
                        ull W0 = wr[a], W1p = wr[NOUT + a], W2p = wr[2 * NOUT + a];
                        A0[i] = ffma2(W0, P01, ffma2(W1p, P12, ffma2(W2p, P23, A0[i])));
                        A1[i] = ffma2(W0, P23, ffma2(W1p, P34, ffma2(W2p, P45, A1[i])));
                        float w0, wd, w1, w2;
                        unpack2(W0, w0, wd);
                        unpack2(W1p, w1, wd);
                        unpack2(W2p, w2, wd);
                        s4[i] = fmaf(w0, f4, fmaf(w1, f5, fmaf(w2, f6, s4[i])));
                    }
                }
            }
        }
        __syncthreads();
    }

    if (act) {
        float* dst = &g_Psplit[(size_t)cs * (NPOS * NOUT)];
#pragma unroll
        for (int i = 0; i < 5; i++) {
            float m0, m1, m2, m3;
            unpack2(A0[i], m0, m1);
            unpack2(A1[i], m2, m3);
            int ch = ag * 5 + i;
            int pb = y * FEAT + xb;
            dst[(pb + 0) * NOUT + ch] = m0;
            dst[(pb + 1) * NOUT + ch] = m1;
            dst[(pb + 2) * NOUT + ch] = m2;
            dst[(pb + 3) * NOUT + ch] = m3;
            dst[(pb + 4) * NOUT + ch] = s4[i];
        }
    }
}

// ------------------ reduce + decode + key + histogram ------------------
__global__ void decode_kernel(const float* __restrict__ anchors)
{
    int i = blockIdx.x * 256 + threadIdx.x;
    if (i >= NBOX) return;
    int p = i / 9, a = i - p * 9;

    float v[5];
#pragma unroll
    for (int d = 0; d < 5; d++) {
        int ch = (d < 4) ? (a * 4 + d) : (36 + a);
        float s = g_bias[ch];
#pragma unroll
        for (int sp = 0; sp < NSPLIT; sp++)
            s += g_Psplit[(size_t)sp * (NPOS * NOUT) + p * NOUT + ch];
        v[d] = s;
    }

    float ay1 = anchors[i * 4 + 0], ax1 = anchors[i * 4 + 1];
    float ay2 = anchors[i * 4 + 2], ax2 = anchors[i * 4 + 3];
    float ah = ay2 - ay1, aw = ax2 - ax1;
    float acy = ay1 + 0.5f * ah, acx = ax1 + 0.5f * aw;
    float cy = v[0] * ah + acy, cx = v[1] * aw + acx;
    float h  = expf(v[2]) * ah, w  = expf(v[3]) * aw;

    float r0 = fminf(fmaxf(cy - 0.5f * h, 0.f), 800.f);
    float r1 = fminf(fmaxf(cx - 0.5f * w, 0.f), 800.f);
    float r2 = fminf(fmaxf(cy + 0.5f * h, 0.f), 800.f);
    float r3 = fminf(fmaxf(cx + 0.5f * w, 0.f), 800.f);

    bool valid = ((r2 - r0) >= 16.f) && ((r3 - r1) >= 16.f);
    float score = valid ? v[4] : -CUDART_INF_F;

    g_roi[i] = make_float4(r0, r1, r2, r3);

    unsigned f   = __float_as_uint(score);
    unsigned asc = f ^ ((f >> 31) ? 0xFFFFFFFFu : 0x80000000u);
    unsigned hi  = ~asc;
    g_key[i] = make_uint2(hi, (unsigned)i);
    atomicAdd(&g_hist[hi >> 16], 1u);
}

// ------------------ cutoff bin ------------------
__global__ void binscan_kernel()
{
    __shared__ unsigned s[256];
    int t = threadIdx.x;
    unsigned sum = 0;
    for (int b = 0; b < 256; b++) sum += g_hist[t * 256 + b];
    s[t] = sum;
    __syncthreads();
    if (t == 0) {
        unsigned cum = 0;
        int cutoff = NBIN - 1;
        for (int g = 0; g < 256; g++) {
            if (cum + s[g] >= (unsigned)PRE) {
                unsigned target = (unsigned)PRE - cum;
                unsigned c2 = 0;
                for (int b = 0; b < 256; b++) {
                    c2 += g_hist[g * 256 + b];
                    if (c2 >= target) { cutoff = g * 256 + b; break; }
                }
                break;
            }
            cum += s[g];
        }
        g_cutoff = (unsigned)cutoff;
    }
}

// ------------------ compact subset ------------------
__global__ void subsel_kernel()
{
    int i = blockIdx.x * 256 + threadIdx.x;
    if (i >= NBOX) return;
    uint2 k = g_key[i];
    if ((k.x >> 16) <= g_cutoff) {
        int pos = atomicAdd(&g_subCnt, 1);
        g_subKey[pos] = k;
    }
}

// ------------------ exact rank, scatter top-6000 ------------------
__global__ void rank_kernel()
{
    const int e = blockIdx.x * 256 + threadIdx.x;
    const int C = g_subCnt;
    uint2 my = (e < C) ? g_subKey[e] : make_uint2(0u, 0u);
    unsigned rank = 0;
    __shared__ uint2 tile[256];
    for (int t0 = 0; t0 < C; t0 += 256) {
        int idx = t0 + threadIdx.x;
        tile[threadIdx.x] = (idx < C) ? g_subKey[idx]
                                      : make_uint2(0xFFFFFFFFu, 0xFFFFFFFFu);
        __syncthreads();
        int lim = min(256, C - t0);
        if (e < C) {
            for (int q = 0; q < lim; q++) {
                uint2 k = tile[q];
                rank += (k.x < my.x) || (k.x == my.x && k.y < my.y);
            }
        }
        __syncthreads();
    }
    if (e < C && rank < (unsigned)PRE) {
        g_sbox[rank] = g_roi[my.y];
        if (my.x < 0xFF800000u)
            atomicOr(&g_validBits[rank >> 5], 1u << (rank & 31));
    }
}

// ------------------ suppression bitmask ------------------
// grid (ceil(PRE/256)=24, NW), 256 threads: whole block shares one j-tile.
__global__ __launch_bounds__(256) void mask_kernel()
{
    const int jt = blockIdx.y;
    const int i  = blockIdx.x * 256 + threadIdx.x;
    __shared__ float4 jb[32];
    int j0 = jt * 32;
    if (threadIdx.x < 32) {
        int jj = j0 + threadIdx.x;
        jb[threadIdx.x] = (jj < PRE) ? g_sbox[jj] : make_float4(0.f, 0.f, 0.f, 0.f);
    }
    __syncthreads();
    if (i >= PRE) return;
    float4 bi = g_sbox[i];
    float areai = (bi.w - bi.y + 1.f) * (bi.z - bi.x + 1.f);
    unsigned word = 0u;
#pragma unroll 8
    for (int q = 0; q < 32; q++) {
        int j = j0 + q;
        if (j > i && j < PRE) {
            float4 bj = jb[q];
            float yy1 = fmaxf(bi.x, bj.x), xx1 = fmaxf(bi.y, bj.y);
            float yy2 = fminf(bi.z, bj.z), xx2 = fminf(bi.w, bj.w);
            float inter = fmaxf(0.f, xx2 - xx1 + 1.f) * fmaxf(0.f, yy2 - yy1 + 1.f);
            float areaj = (bj.w - bj.y + 1.f) * (bj.z - bj.x + 1.f);
            float iou = inter / (areai + areaj - inter);
            if (iou > 0.7f) word |= (1u << q);
        }
    }
    g_mask[(size_t)i * NW + jt] = word;
}

// ------------------ serial greedy NMS (one warp, uint4 row ORs) ------------------
__global__ void nms_kernel(float* __restrict__ out)
{
    const int lane = threadIdx.x;
    __shared__ unsigned rem[NW], val[NW];
    for (int w = lane; w < NW; w += 32) { rem[w] = 0u; val[w] = g_validBits[w]; }
    for (int k = lane; k < POST * 4; k += 32) out[k] = 0.f;
    __syncwarp();

    int kept = 0;
    for (int w = 0; w < NW && kept < POST; w++) {
        while (kept < POST) {
            unsigned avail = val[w] & ~rem[w];
            if (!avail) break;
            int b = __ffs(avail) - 1;
            int i = w * 32 + b;
            if (lane == 0) {
                float4 bx = g_sbox[i];
                out[kept * 4 + 0] = bx.x;
                out[kept * 4 + 1] = bx.y;
                out[kept * 4 + 2] = bx.z;
                out[kept * 4 + 3] = bx.w;
                rem[w] |= (1u << b);
            }
            __syncwarp();
            const uint4* m4 = (const uint4*)(g_mask + (size_t)i * NW);
            for (int q = lane; q < NW / 4; q += 32) {
                uint4 v = __ldg(m4 + q);
                rem[4 * q + 0] |= v.x;
                rem[4 * q + 1] |= v.y;
                rem[4 * q + 2] |= v.z;
                rem[4 * q + 3] |= v.w;
            }
            __syncwarp();
            kept++;
        }
    }
}

// ------------------ launch ------------------
extern "C" void kernel_launch(void* const* d_in, const int* in_sizes, int n_in,
                              void* d_out, int out_size)
{
    const float* feat    = (const float*)d_in[0];
    const float* anchors = (const float*)d_in[1];
    const float* W1      = (const float*)d_in[2];
    const float* b1      = (const float*)d_in[3];
    const float* Wreg    = (const float*)d_in[4];
    const float* breg    = (const float*)d_in[5];
    const float* Wcls    = (const float*)d_in[6];
    const float* bcls    = (const float*)d_in[7];
    float* out = (float*)d_out;

    zero_kernel<<<(NBIN + 255) / 256, 256>>>();
    fold_kernel<<<144, 192>>>(W1, Wreg, Wcls);
    bias_kernel<<<1, 64>>>(Wreg, breg, Wcls, bcls, b1);
    main_kernel<<<dim3(16, 25), 192>>>(feat);
    decode_kernel<<<(NBOX + 255) / 256, 256>>>(anchors);
    binscan_kernel<<<1, 256>>>();
    subsel_kernel<<<(NBOX + 255) / 256, 256>>>();
    rank_kernel<<<(NBOX + 255) / 256, 256>>>();
    mask_kernel<<<dim3((PRE + 255) / 256, NW), 256>>>();
    nms_kernel<<<1, 32>>>(out);
}

// round 4
// speedup vs baseline: 1.7787x; 1.0301x over previous
#include <cuda_runtime.h>
#include <cuda_bf16.h>
#include <math_constants.h>

#define FEAT 50
#define NPOS 2500
#define NBOX 22500
#define CIN 2048
#define CMID 1024
#define KJ (CIN*9)        // 18432
#define NOUT 45
#define NSPLIT 16
#define PRE 6000
#define POST 300
#define NW 188            // ceil(6000/32)
#define MASKW 192         // padded row stride for mask
#define NBIN 65536

typedef unsigned long long ull;

// ---------- packed fp32x2 helpers ----------
__device__ __forceinline__ ull pack2(float lo, float hi) {
    ull d; asm("mov.b64 %0, {%1, %2};" : "=l"(d) : "f"(lo), "f"(hi)); return d;
}
__device__ __forceinline__ void unpack2(ull p, float& lo, float& hi) {
    asm("mov.b64 {%0, %1}, %2;" : "=f"(lo), "=f"(hi) : "l"(p));
}
__device__ __forceinline__ ull ffma2(ull a, ull b, ull c) {
    ull d; asm("fma.rn.f32x2 %0, %1, %2, %3;" : "=l"(d) : "l"(a), "l"(b), "l"(c)); return d;
}
__device__ __forceinline__ ull fadd2(ull a, ull b) {
    ull d; asm("add.rn.f32x2 %0, %1, %2;" : "=l"(d) : "l"(a), "l"(b)); return d;
}

// ------------------ scratch ------------------
__device__ ull        g_WeffU[(size_t)KJ * NOUT];   // duplicated (w,w) per entry
__device__ float      g_bias[NOUT];
__device__ float      g_Psplit[NSPLIT * NPOS * NOUT];
__device__ float4     g_roi[NBOX];
__device__ ull        g_keyU[NBOX];                 // (desc-score-bits << 32) | idx
__device__ unsigned   g_hist[NBIN];
__device__ unsigned   g_cutoff;
__device__ int        g_subCnt;
__device__ ull        g_subKeyU[NBOX];
__device__ float4     g_sbox[PRE];
__device__ unsigned   g_validBits[NW];
__device__ unsigned   g_mask[(size_t)PRE * MASKW];  // padding words never written (stay 0)

// ------------------ zero scratch ------------------
__global__ void zero_kernel() {
    int i = blockIdx.x * 256 + threadIdx.x;
    if (i < NBIN) g_hist[i] = 0u;
    if (i < NW)   g_validBits[i] = 0u;
    if (i == 0)   g_subCnt = 0;
}

// ------------------ fold: WeffU = Whead @ W1, k-packed FFMA2 ------------------
// grid 144 (128 j-cols each), block 384 = 3 out-groups x 128 cols.
__global__ __launch_bounds__(384) void fold_kernel(
    const float* __restrict__ W1, const float* __restrict__ Wreg,
    const float* __restrict__ Wcls)
{
    const int t = threadIdx.x;
    const int g = t >> 7;           // 0..2
    const int j = t & 127;
    const int j0 = blockIdx.x * 128;

    __shared__ ull sB[16][128];     // (W1[2cp][j], W1[2cp+1][j])
    __shared__ ull sH[45][17];      // (H[s][2cp], H[s][2cp+1]), padded

    ull acc[15];
#pragma unroll
    for (int s = 0; s < 15; s++) acc[s] = 0ULL;

    for (int ct = 0; ct < 32; ct++) {
        const int k0 = ct * 32;
        for (int idx = t; idx < 2048; idx += 384) {
            int cp = idx >> 7, jj = idx & 127;
            float lo = W1[(size_t)(k0 + 2 * cp)     * KJ + j0 + jj];
            float hi = W1[(size_t)(k0 + 2 * cp + 1) * KJ + j0 + jj];
            sB[cp][jj] = pack2(lo, hi);
        }
        for (int idx = t; idx < 720; idx += 384) {
            int s = idx >> 4, cp = idx & 15;
            int k = k0 + 2 * cp;
            float lo, hi;
            if (s < 36) { lo = Wreg[s * CMID + k]; hi = Wreg[s * CMID + k + 1]; }
            else {
                int a = s - 36;
                lo = Wcls[(2 * a + 1) * CMID + k];
                hi = Wcls[(2 * a + 1) * CMID + k + 1];
            }
            sH[s][cp] = pack2(lo, hi);
        }
        __syncthreads();

        ull al[15];
#pragma unroll
        for (int s = 0; s < 15; s++) al[s] = 0ULL;
#pragma unroll 4
        for (int cp = 0; cp < 16; cp++) {
            ull B = sB[cp][j];
#pragma unroll
            for (int s = 0; s < 15; s++)
                al[s] = ffma2(sH[g * 15 + s][cp], B, al[s]);
        }
#pragma unroll
        for (int s = 0; s < 15; s++) acc[s] = fadd2(acc[s], al[s]);
        __syncthreads();
    }

#pragma unroll
    for (int s = 0; s < 15; s++) {
        float lo, hi; unpack2(acc[s], lo, hi);
        float v = lo + hi;
        g_WeffU[(size_t)(j0 + j) * NOUT + g * 15 + s] = pack2(v, v);
    }
}

// ------------------ effective biases ------------------
__global__ void bias_kernel(const float* __restrict__ Wreg, const float* __restrict__ breg,
                            const float* __restrict__ Wcls, const float* __restrict__ bcls,
                            const float* __restrict__ b1)
{
    int s = threadIdx.x;
    if (s >= NOUT) return;
    const float* row;
    float hb;
    if (s < 36) { row = Wreg + s * CMID; hb = breg[s]; }
    else        { int a = s - 36; row = Wcls + (2 * a + 1) * CMID; hb = bcls[2 * a + 1]; }
    float acc = 0.f;
    for (int k = 0; k < CMID; k++) acc = fmaf(row[k], b1[k], acc);
    g_bias[s] = hb + acc;
}

// ------------------ main folded conv: pre-packed E/O feature arrays ------------------
// grid (16 csplit, 25 y-pairs), block 160: og(15 x 3outs) x xg(5 x 10cols) x ys(2).
__global__ __launch_bounds__(160, 3) void main_kernel(const float* __restrict__ feat)
{
    const int t  = threadIdx.x;
    const int cs = blockIdx.x;
    const int yg = blockIdx.y;

    const int og = t % 15;
    const int xg = (t / 15) % 5;
    const int ys = t / 75;            // 0..1 for t<150
    const bool act = (t < 150);
    const int y  = yg * 2 + ys;
    const int mb = xg * 5;            // pair base (x = 2*mb)

    __shared__ ull sE[8 * 4 * 25];    // (f(2c), f(2c+1))
    __shared__ ull sO[8 * 4 * 26];    // (f(2c-1), f(2c))
    __shared__ ull sW[8 * 9 * 45];    // duplicated weights

    ull acc[3][5];
#pragma unroll
    for (int i = 0; i < 3; i++)
#pragma unroll
        for (int m = 0; m < 5; m++) acc[i][m] = 0ULL;

    for (int ct = 0; ct < 16; ct++) {
        const int c0 = cs * 128 + ct * 8;
        // stage E (aligned float2 loads, gx in [0,49] always)
        for (int idx = t; idx < 800; idx += 160) {
            int cr = idx / 25, c = idx - cr * 25;
            int cc = cr >> 2, r = cr & 3;
            int gy = yg * 2 - 1 + r;
            ull v = 0ULL;
            if (gy >= 0 && gy < FEAT) {
                const float2 p = *(const float2*)&feat[(size_t)(c0 + cc) * NPOS + gy * FEAT + 2 * c];
                v = pack2(p.x, p.y);
            }
            sE[idx] = v;
        }
        // stage O (scalar loads with halo)
        for (int idx = t; idx < 832; idx += 160) {
            int cr = idx / 26, c = idx - cr * 26;
            int cc = cr >> 2, r = cr & 3;
            int gy = yg * 2 - 1 + r;
            float lo = 0.f, hi = 0.f;
            if (gy >= 0 && gy < FEAT) {
                const float* rp = &feat[(size_t)(c0 + cc) * NPOS + gy * FEAT];
                int gx = 2 * c - 1;
                if (gx >= 0)       lo = rp[gx];
                if (gx + 1 < FEAT) hi = rp[gx + 1];
            }
            sO[idx] = pack2(lo, hi);
        }
        // stage weights (already duplicated)
        {
            const ull* src = &g_WeffU[(size_t)c0 * 9 * NOUT];
            for (int idx = t; idx < 8 * 9 * 45; idx += 160) sW[idx] = src[idx];
        }
        __syncthreads();

        if (act) {
            ull al[3][5];
#pragma unroll
            for (int i = 0; i < 3; i++)
#pragma unroll
                for (int m = 0; m < 5; m++) al[i][m] = 0ULL;

            for (int cc = 0; cc < 8; cc++) {
#pragma unroll
                for (int ky = 0; ky < 3; ky++) {
                    const ull* eb = &sE[(cc * 4 + ys + ky) * 25 + mb];
                    const ull* ob = &sO[(cc * 4 + ys + ky) * 26 + mb];
                    const ull* wb = &sW[(cc * 9 + ky * 3) * NOUT];
                    ull w00 = wb[og*3+0], w01 = wb[NOUT+og*3+0], w02 = wb[2*NOUT+og*3+0];
                    ull w10 = wb[og*3+1], w11 = wb[NOUT+og*3+1], w12 = wb[2*NOUT+og*3+1];
                    ull w20 = wb[og*3+2], w21 = wb[NOUT+og*3+2], w22 = wb[2*NOUT+og*3+2];
                    ull Oc = ob[0];
#pragma unroll
                    for (int m = 0; m < 5; m++) {
                        ull E  = eb[m];
                        ull On = ob[m + 1];
                        al[0][m] = ffma2(w00, Oc, ffma2(w01, E, ffma2(w02, On, al[0][m])));
                        al[1][m] = ffma2(w10, Oc, ffma2(w11, E, ffma2(w12, On, al[1][m])));
                        al[2][m] = ffma2(w20, Oc, ffma2(w21, E, ffma2(w22, On, al[2][m])));
                        Oc = On;
                    }
                }
            }
#pragma unroll
            for (int i = 0; i < 3; i++)
#pragma unroll
                for (int m = 0; m < 5; m++) acc[i][m] = fadd2(acc[i][m], al[i][m]);
        }
        __syncthreads();
    }

    if (act) {
        float* dst = &g_Psplit[(size_t)cs * (NPOS * NOUT)];
        int pb = y * FEAT + 2 * mb;
#pragma unroll
        for (int i = 0; i < 3; i++) {
            int ch = og * 3 + i;
#pragma unroll
            for (int m = 0; m < 5; m++) {
                float lo, hi; unpack2(acc[i][m], lo, hi);
                dst[(pb + 2 * m)     * NOUT + ch] = lo;
                dst[(pb + 2 * m + 1) * NOUT + ch] = hi;
            }
        }
    }
}

// ------------------ reduce + decode + key + histogram ------------------
__global__ void decode_kernel(const float* __restrict__ anchors)
{
    int i = blockIdx.x * 256 + threadIdx.x;
    if (i >= NBOX) return;
    int p = i / 9, a = i - p * 9;

    float v[5];
#pragma unroll
    for (int d = 0; d < 5; d++) {
        int ch = (d < 4) ? (a * 4 + d) : (36 + a);
        float s = g_bias[ch];
#pragma unroll
        for (int sp = 0; sp < NSPLIT; sp++)
            s += g_Psplit[(size_t)sp * (NPOS * NOUT) + p * NOUT + ch];
        v[d] = s;
    }

    float ay1 = anchors[i * 4 + 0], ax1 = anchors[i * 4 + 1];
    float ay2 = anchors[i * 4 + 2], ax2 = anchors[i * 4 + 3];
    float ah = ay2 - ay1, aw = ax2 - ax1;
    float acy = ay1 + 0.5f * ah, acx = ax1 + 0.5f * aw;
    float cy = v[0] * ah + acy, cx = v[1] * aw + acx;
    float h  = expf(v[2]) * ah, w  = expf(v[3]) * aw;

    float r0 = fminf(fmaxf(cy - 0.5f * h, 0.f), 800.f);
    float r1 = fminf(fmaxf(cx - 0.5f * w, 0.f), 800.f);
    float r2 = fminf(fmaxf(cy + 0.5f * h, 0.f), 800.f);
    float r3 = fminf(fmaxf(cx + 0.5f * w, 0.f), 800.f);

    bool valid = ((r2 - r0) >= 16.f) && ((r3 - r1) >= 16.f);
    float score = valid ? v[4] : -CUDART_INF_F;

    g_roi[i] = make_float4(r0, r1, r2, r3);

    unsigned f   = __float_as_uint(score);
    unsigned asc = f ^ ((f >> 31) ? 0xFFFFFFFFu : 0x80000000u);
    unsigned hi  = ~asc;
    g_keyU[i] = ((ull)hi << 32) | (unsigned)i;
    atomicAdd(&g_hist[hi >> 16], 1u);
}

// ------------------ cutoff bin ------------------
__global__ void binscan_kernel()
{
    __shared__ unsigned s[256];
    int t = threadIdx.x;
    unsigned sum = 0;
    for (int b = 0; b < 256; b++) sum += g_hist[t * 256 + b];
    s[t] = sum;
    __syncthreads();
    if (t == 0) {
        unsigned cum = 0;
        int cutoff = NBIN - 1;
        for (int g = 0; g < 256; g++) {
            if (cum + s[g] >= (unsigned)PRE) {
                unsigned target = (unsigned)PRE - cum;
                unsigned c2 = 0;
                for (int b = 0; b < 256; b++) {
                    c2 += g_hist[g * 256 + b];
                    if (c2 >= target) { cutoff = g * 256 + b; break; }
                }
                break;
            }
            cum += s[g];
        }
        g_cutoff = (unsigned)cutoff;
    }
}

// ------------------ compact subset ------------------
__global__ void subsel_kernel()
{
    int i = blockIdx.x * 256 + threadIdx.x;
    if (i >= NBOX) return;
    ull k = g_keyU[i];
    if ((unsigned)(k >> 48) <= g_cutoff) {
        int pos = atomicAdd(&g_subCnt, 1);
        g_subKeyU[pos] = k;
    }
}

// ------------------ exact rank, scatter top-6000 ------------------
__global__ void rank_kernel()
{
    const int C = g_subCnt;
    if (blockIdx.x * 256 >= C) return;
    const int e = blockIdx.x * 256 + threadIdx.x;
    ull my = (e < C) ? g_subKeyU[e] : 0ULL;
    unsigned rank = 0;
    __shared__ ull tile[256];
    for (int t0 = 0; t0 < C; t0 += 256) {
        int idx = t0 + threadIdx.x;
        tile[threadIdx.x] = (idx < C) ? g_subKeyU[idx] : ~0ULL;
        __syncthreads();
        int lim = min(256, C - t0);
        if (e < C) {
            for (int q = 0; q < lim; q++)
                rank += (tile[q] < my);
        }
        __syncthreads();
    }
    if (e < C && rank < (unsigned)PRE) {
        g_sbox[rank] = g_roi[(unsigned)my];
        if ((unsigned)(my >> 32) < 0xFF800000u)
            atomicOr(&g_validBits[rank >> 5], 1u << (rank & 31));
    }
}

// ------------------ suppression bitmask (stride MASKW) ------------------
__global__ __launch_bounds__(256) void mask_kernel()
{
    const int jt = blockIdx.y;
    const int i  = blockIdx.x * 256 + threadIdx.x;
    __shared__ float4 jb[32];
    int j0 = jt * 32;
    if (threadIdx.x < 32) {
        int jj = j0 + threadIdx.x;
        jb[threadIdx.x] = (jj < PRE) ? g_sbox[jj] : make_float4(0.f, 0.f, 0.f, 0.f);
    }
    __syncthreads();
    if (i >= PRE) return;
    float4 bi = g_sbox[i];
    float areai = (bi.w - bi.y + 1.f) * (bi.z - bi.x + 1.f);
    unsigned word = 0u;
#pragma unroll 8
    for (int q = 0; q < 32; q++) {
        int j = j0 + q;
        if (j > i && j < PRE) {
            float4 bj = jb[q];
            float yy1 = fmaxf(bi.x, bj.x), xx1 = fmaxf(bi.y, bj.y);
            float yy2 = fminf(bi.z, bj.z), xx2 = fminf(bi.w, bj.w);
            float inter = fmaxf(0.f, xx2 - xx1 + 1.f) * fmaxf(0.f, yy2 - yy1 + 1.f);
            float areaj = (bj.w - bj.y + 1.f) * (bj.z - bj.x + 1.f);
            float iou = inter / (areai + areaj - inter);
            if (iou > 0.7f) word |= (1u << q);
        }
    }
    g_mask[(size_t)i * MASKW + jt] = word;
}

// ------------------ serial greedy NMS: one warp, register-resident bitsets ------------------
__global__ void nms_kernel(float* __restrict__ out)
{
    const int lane = threadIdx.x;
    unsigned val[6], rem[6];
#pragma unroll
    for (int q = 0; q < 6; q++) {
        int w = 6 * lane + q;
        val[q] = (w < NW) ? g_validBits[w] : 0u;
        rem[q] = 0u;
    }
    for (int k = lane; k < POST * 4; k += 32) out[k] = 0.f;
    __syncwarp();

    for (int kept = 0; kept < POST; kept++) {
        int cand = 0x7FFFFFFF;
#pragma unroll
        for (int q = 0; q < 6; q++) {
            unsigned a = val[q] & ~rem[q];
            if (a && cand == 0x7FFFFFFF)
                cand = (6 * lane + q) * 32 + __ffs(a) - 1;
        }
        int i = __reduce_min_sync(0xFFFFFFFFu, cand);
        if (i == 0x7FFFFFFF) break;

        int ql = (i >> 5) - 6 * lane;
        if (ql >= 0 && ql < 6) rem[ql] |= (1u << (i & 31));

        if (lane == 0) {
            float4 bx = g_sbox[i];
            *(float4*)&out[kept * 4] = bx;
        }
        const uint2* row = (const uint2*)(g_mask + (size_t)i * MASKW);
        uint2 a0 = __ldg(&row[3 * lane]);
        uint2 a1 = __ldg(&row[3 * lane + 1]);
        uint2 a2 = __ldg(&row[3 * lane + 2]);
        rem[0] |= a0.x; rem[1] |= a0.y;
        rem[2] |= a1.x; rem[3] |= a1.y;
        rem[4] |= a2.x; rem[5] |= a2.y;
    }
}

// ------------------ launch ------------------
extern "C" void kernel_launch(void* const* d_in, const int* in_sizes, int n_in,
                              void* d_out, int out_size)
{
    const float* feat    = (const float*)d_in[0];
    const float* anchors = (const float*)d_in[1];
    const float* W1      = (const float*)d_in[2];
    const float* b1      = (const float*)d_in[3];
    const float* Wreg    = (const float*)d_in[4];
    const float* breg    = (const float*)d_in[5];
    const float* Wcls    = (const float*)d_in[6];
    const float* bcls    = (const float*)d_in[7];
    float* out = (float*)d_out;

    zero_kernel<<<(NBIN + 255) / 256, 256>>>();
    fold_kernel<<<144, 384>>>(W1, Wreg, Wcls);
    bias_kernel<<<1, 64>>>(Wreg, breg, Wcls, bcls, b1);
    main_kernel<<<dim3(16, 25), 160>>>(feat);
    decode_kernel<<<(NBOX + 255) / 256, 256>>>(anchors);
    binscan_kernel<<<1, 256>>>();
    subsel_kernel<<<(NBOX + 255) / 256, 256>>>();
    rank_kernel<<<(NBOX + 255) / 256, 256>>>();
    mask_kernel<<<dim3((PRE + 255) / 256, NW), 256>>>();
    nms_kernel<<<1, 32>>>(out);
}

// round 5
// speedup vs baseline: 1.8345x; 1.0314x over previous
#include <cuda_runtime.h>
#include <cuda_bf16.h>
#include <math_constants.h>

#define FEAT 50
#define NPOS 2500
#define NBOX 22500
#define CIN 2048
#define CMID 1024
#define KJ (CIN*9)        // 18432
#define NOUT 45
#define NSPLIT 16
#define PRE 6000
#define POST 300
#define NW 188
#define MASKW 192
#define NBIN 65536
#define WPAD 60           // padded weight row: og*4+i, 15 og

typedef unsigned long long ull;

__device__ __forceinline__ ull pack2(float lo, float hi) {
    ull d; asm("mov.b64 %0, {%1, %2};" : "=l"(d) : "f"(lo), "f"(hi)); return d;
}
__device__ __forceinline__ void unpack2(ull p, float& lo, float& hi) {
    asm("mov.b64 {%0, %1}, %2;" : "=f"(lo), "=f"(hi) : "l"(p));
}
__device__ __forceinline__ ull ffma2(ull a, ull b, ull c) {
    ull d; asm("fma.rn.f32x2 %0, %1, %2, %3;" : "=l"(d) : "l"(a), "l"(b), "l"(c)); return d;
}

// ------------------ scratch ------------------
__device__ float      g_WfP0[(size_t)KJ * NOUT];    // fold partial (k < 512)
__device__ float      g_WfP1[(size_t)KJ * NOUT];    // fold partial (k >= 512)
__device__ ull        g_WeffP[(size_t)CIN * 9 * WPAD]; // padded, duplicated (w,w)
__device__ float      g_bias[NOUT];
__device__ float      g_Psplit[NSPLIT * NPOS * NOUT];
__device__ float4     g_roi[NBOX];
__device__ ull        g_keyU[NBOX];
__device__ unsigned   g_hist[NBIN];
__device__ unsigned   g_gsum[256];
__device__ unsigned   g_cutoff;
__device__ int        g_subCnt;
__device__ ull        g_subKeyU[NBOX];
__device__ float4     g_sbox[PRE];
__device__ unsigned   g_validBits[NW];
__device__ unsigned   g_mask[(size_t)PRE * MASKW];

// ------------------ zero scratch ------------------
__global__ void zero_kernel() {
    int i = blockIdx.x * 256 + threadIdx.x;
    if (i < NBIN) g_hist[i] = 0u;
    if (i < NW)   g_validBits[i] = 0u;
    if (i == 0)   g_subCnt = 0;
}

// ------------------ fold: warp-uniform-H broadcast, k-packed FFMA2 ------------------
// grid (144, 2): 144 j-blocks of 128 cols x 2 k-halves. block 192 = 3 s-groups x 64.
// Thread: 2 adjacent columns x 15 outputs.
__global__ __launch_bounds__(192) void fold_kernel(
    const float* __restrict__ W1, const float* __restrict__ Wreg,
    const float* __restrict__ Wcls)
{
    const int t  = threadIdx.x;
    const int g  = t >> 6;          // s-group 0..2 (uniform per warp)
    const int u  = t & 63;          // column pair index
    const int j0 = blockIdx.x * 128;
    const int kh = blockIdx.y;      // k-half

    __shared__ ull sB[16][128];     // (W1[k0+2cp][col], W1[k0+2cp+1][col])
    __shared__ ull sH[16 * 48];     // [cp*48 + g*16 + s]

    ull a0[15], a1[15];
#pragma unroll
    for (int s = 0; s < 15; s++) { a0[s] = 0ULL; a1[s] = 0ULL; }

    for (int ct = 0; ct < 16; ct++) {
        const int k0 = kh * 512 + ct * 32;
        for (int idx = t; idx < 2048; idx += 192) {
            int cp = idx >> 7, col = idx & 127;
            float lo = W1[(size_t)(k0 + 2 * cp)     * KJ + j0 + col];
            float hi = W1[(size_t)(k0 + 2 * cp + 1) * KJ + j0 + col];
            sB[cp][col] = pack2(lo, hi);
        }
        for (int idx = t; idx < 720; idx += 192) {
            int s = idx >> 4, cp = idx & 15;
            int k = k0 + 2 * cp;
            float lo, hi;
            if (s < 36) { lo = Wreg[s * CMID + k]; hi = Wreg[s * CMID + k + 1]; }
            else {
                int a = s - 36;
                lo = Wcls[(2 * a + 1) * CMID + k];
                hi = Wcls[(2 * a + 1) * CMID + k + 1];
            }
            sH[cp * 48 + (s / 15) * 16 + (s % 15)] = pack2(lo, hi);
        }
        __syncthreads();

#pragma unroll 4
        for (int cp = 0; cp < 16; cp++) {
            ulonglong2 B = *(const ulonglong2*)&sB[cp][2 * u];
            const ull* hp = &sH[cp * 48 + g * 16];
#pragma unroll
            for (int s = 0; s < 15; s += 2) {
                if (s < 14) {
                    ulonglong2 h2 = *(const ulonglong2*)&hp[s];
                    a0[s]   = ffma2(h2.x, B.x, a0[s]);
                    a1[s]   = ffma2(h2.x, B.y, a1[s]);
                    a0[s+1] = ffma2(h2.y, B.x, a0[s+1]);
                    a1[s+1] = ffma2(h2.y, B.y, a1[s+1]);
                } else {
                    ull h = hp[s];
                    a0[s] = ffma2(h, B.x, a0[s]);
                    a1[s] = ffma2(h, B.y, a1[s]);
                }
            }
        }
        __syncthreads();
    }

    float* dst = kh ? g_WfP1 : g_WfP0;
    const int jA = j0 + 2 * u;
#pragma unroll
    for (int s = 0; s < 15; s++) {
        float l0, h0, l1, h1;
        unpack2(a0[s], l0, h0);
        unpack2(a1[s], l1, h1);
        dst[(size_t)jA * NOUT + g * 15 + s]       = l0 + h0;
        dst[(size_t)(jA + 1) * NOUT + g * 15 + s] = l1 + h1;
    }
}

// ------------------ sum partials -> padded duplicated weights ------------------
__global__ void sumw_kernel()
{
    int idx = blockIdx.x * 256 + threadIdx.x;
    if (idx >= CIN * 9 * NOUT) return;
    int c   = idx / 405;
    int r   = idx - c * 405;
    int ky  = r / 135;
    int r2  = r - ky * 135;
    int kx  = r2 / 45;
    int ch  = r2 - kx * 45;
    size_t j = (size_t)(c * 9 + ky * 3 + kx) * NOUT + ch;
    float v = g_WfP0[j] + g_WfP1[j];
    int og = ch / 3, i = ch - og * 3;
    g_WeffP[(size_t)((c * 3 + ky) * 3 + kx) * WPAD + og * 4 + i] = pack2(v, v);
}

// ------------------ effective biases ------------------
__global__ void bias_kernel(const float* __restrict__ Wreg, const float* __restrict__ breg,
                            const float* __restrict__ Wcls, const float* __restrict__ bcls,
                            const float* __restrict__ b1)
{
    int s = threadIdx.x;
    if (s >= NOUT) return;
    const float* row;
    float hb;
    if (s < 36) { row = Wreg + s * CMID; hb = breg[s]; }
    else        { int a = s - 36; row = Wcls + (2 * a + 1) * CMID; hb = bcls[2 * a + 1]; }
    float acc = 0.f;
    for (int k = 0; k < CMID; k++) acc = fmaf(row[k], b1[k], acc);
    g_bias[s] = hb + acc;
}

// ------------------ main folded conv ------------------
__global__ __launch_bounds__(160, 3) void main_kernel(const float* __restrict__ feat)
{
    const int t  = threadIdx.x;
    const int cs = blockIdx.x;
    const int yg = blockIdx.y;

    const int og = t % 15;
    const int xg = (t / 15) % 5;
    const int ys = t / 75;
    const bool act = (t < 150);
    const int y  = yg * 2 + ys;
    const int mb = xg * 5;

    __shared__ ull sE[8 * 4 * 25];
    __shared__ ull sO[8 * 4 * 26];
    __shared__ ull sW[8 * 9 * WPAD];   // padded weights

    ull acc[3][5];
#pragma unroll
    for (int i = 0; i < 3; i++)
#pragma unroll
        for (int m = 0; m < 5; m++) acc[i][m] = 0ULL;

    for (int ct = 0; ct < 16; ct++) {
        const int c0 = cs * 128 + ct * 8;
        for (int idx = t; idx < 800; idx += 160) {
            int cr = idx / 25, c = idx - cr * 25;
            int cc = cr >> 2, r = cr & 3;
            int gy = yg * 2 - 1 + r;
            ull v = 0ULL;
            if (gy >= 0 && gy < FEAT) {
                const float2 p = *(const float2*)&feat[(size_t)(c0 + cc) * NPOS + gy * FEAT + 2 * c];
                v = pack2(p.x, p.y);
            }
            sE[idx] = v;
        }
        for (int idx = t; idx < 832; idx += 160) {
            int cr = idx / 26, c = idx - cr * 26;
            int cc = cr >> 2, r = cr & 3;
            int gy = yg * 2 - 1 + r;
            float lo = 0.f, hi = 0.f;
            if (gy >= 0 && gy < FEAT) {
                const float* rp = &feat[(size_t)(c0 + cc) * NPOS + gy * FEAT];
                int gx = 2 * c - 1;
                if (gx >= 0)       lo = rp[gx];
                if (gx + 1 < FEAT) hi = rp[gx + 1];
            }
            sO[idx] = pack2(lo, hi);
        }
        {
            const ull* src = &g_WeffP[(size_t)c0 * 9 * WPAD];
            for (int idx = t; idx < 8 * 9 * WPAD; idx += 160) sW[idx] = src[idx];
        }
        __syncthreads();

        if (act) {
            ull al[3][5];
#pragma unroll
            for (int i = 0; i < 3; i++)
#pragma unroll
                for (int m = 0; m < 5; m++) al[i][m] = 0ULL;

            for (int cc = 0; cc < 8; cc++) {
#pragma unroll
                for (int ky = 0; ky < 3; ky++) {
                    const ull* eb = &sE[(cc * 4 + ys + ky) * 25 + mb];
                    const ull* ob = &sO[(cc * 4 + ys + ky) * 26 + mb];
                    const ull* wb = &sW[(size_t)((cc * 3 + ky) * 3) * WPAD + og * 4];
                    ulonglong2 wA = *(const ulonglong2*)&wb[0];           // kx=0: i0,i1
                    ull        wa2 = wb[2];                               // kx=0: i2
                    ulonglong2 wB = *(const ulonglong2*)&wb[WPAD];        // kx=1
                    ull        wb2 = wb[WPAD + 2];
                    ulonglong2 wC = *(const ulonglong2*)&wb[2 * WPAD];    // kx=2
                    ull        wc2 = wb[2 * WPAD + 2];
                    ull Oc = ob[0];
#pragma unroll
                    for (int m = 0; m < 5; m++) {
                        ull E  = eb[m];
                        ull On = ob[m + 1];
                        al[0][m] = ffma2(wA.x, Oc, ffma2(wB.x, E, ffma2(wC.x, On, al[0][m])));
                        al[1][m] = ffma2(wA.y, Oc, ffma2(wB.y, E, ffma2(wC.y, On, al[1][m])));
                        al[2][m] = ffma2(wa2,  Oc, ffma2(wb2,  E, ffma2(wc2,  On, al[2][m])));
                        Oc = On;
                    }
                }
            }
#pragma unroll
            for (int i = 0; i < 3; i++)
#pragma unroll
                for (int m = 0; m < 5; m++) {
                    float xl, xh, yl, yh;
                    unpack2(acc[i][m], xl, xh);
                    unpack2(al[i][m], yl, yh);
                    acc[i][m] = pack2(xl + yl, xh + yh);
                }
        }
        __syncthreads();
    }

    if (act) {
        float* dst = &g_Psplit[(size_t)cs * (NPOS * NOUT)];
        int pb = y * FEAT + 2 * mb;
#pragma unroll
        for (int i = 0; i < 3; i++) {
            int ch = og * 3 + i;
#pragma unroll
            for (int m = 0; m < 5; m++) {
                float lo, hi; unpack2(acc[i][m], lo, hi);
                dst[(pb + 2 * m)     * NOUT + ch] = lo;
                dst[(pb + 2 * m + 1) * NOUT + ch] = hi;
            }
        }
    }
}

// ------------------ reduce + decode + key + histogram ------------------
__global__ void decode_kernel(const float* __restrict__ anchors)
{
    int i = blockIdx.x * 256 + threadIdx.x;
    if (i >= NBOX) return;
    int p = i / 9, a = i - p * 9;

    float v[5];
#pragma unroll
    for (int d = 0; d < 5; d++) {
        int ch = (d < 4) ? (a * 4 + d) : (36 + a);
        float s = g_bias[ch];
#pragma unroll
        for (int sp = 0; sp < NSPLIT; sp++)
            s += g_Psplit[(size_t)sp * (NPOS * NOUT) + p * NOUT + ch];
        v[d] = s;
    }

    float ay1 = anchors[i * 4 + 0], ax1 = anchors[i * 4 + 1];
    float ay2 = anchors[i * 4 + 2], ax2 = anchors[i * 4 + 3];
    float ah = ay2 - ay1, aw = ax2 - ax1;
    float acy = ay1 + 0.5f * ah, acx = ax1 + 0.5f * aw;
    float cy = v[0] * ah + acy, cx = v[1] * aw + acx;
    float h  = expf(v[2]) * ah, w  = expf(v[3]) * aw;

    float r0 = fminf(fmaxf(cy - 0.5f * h, 0.f), 800.f);
    float r1 = fminf(fmaxf(cx - 0.5f * w, 0.f), 800.f);
    float r2 = fminf(fmaxf(cy + 0.5f * h, 0.f), 800.f);
    float r3 = fminf(fmaxf(cx + 0.5f * w, 0.f), 800.f);

    bool valid = ((r2 - r0) >= 16.f) && ((r3 - r1) >= 16.f);
    float score = valid ? v[4] : -CUDART_INF_F;

    g_roi[i] = make_float4(r0, r1, r2, r3);

    unsigned f   = __float_as_uint(score);
    unsigned asc = f ^ ((f >> 31) ? 0xFFFFFFFFu : 0x80000000u);
    unsigned hi  = ~asc;
    g_keyU[i] = ((ull)hi << 32) | (unsigned)i;
    atomicAdd(&g_hist[hi >> 16], 1u);
}

// ------------------ coalesced group sums ------------------
__global__ void gsum_kernel()
{
    int b = blockIdx.x, t = threadIdx.x;
    unsigned v = g_hist[b * 256 + t];
#pragma unroll
    for (int o = 16; o > 0; o >>= 1) v += __shfl_down_sync(0xFFFFFFFFu, v, o);
    __shared__ unsigned sp[8];
    if ((t & 31) == 0) sp[t >> 5] = v;
    __syncthreads();
    if (t == 0) {
        unsigned s = 0;
#pragma unroll
        for (int q = 0; q < 8; q++) s += sp[q];
        g_gsum[b] = s;
    }
}

// ------------------ cutoff bin ------------------
__global__ void binscan_kernel()
{
    __shared__ unsigned sg[256], sh[256];
    __shared__ int Gs, Ts;
    int t = threadIdx.x;
    sg[t] = g_gsum[t];
    __syncthreads();
    if (t == 0) {
        unsigned cum = 0;
        int G = 255, tgt = 1;
        for (int g = 0; g < 256; g++) {
            if (cum + sg[g] >= (unsigned)PRE) { G = g; tgt = PRE - cum; break; }
            cum += sg[g];
        }
        Gs = G; Ts = tgt;
    }
    __syncthreads();
    sh[t] = g_hist[Gs * 256 + t];
    __syncthreads();
    if (t == 0) {
        unsigned c2 = 0;
        int cutoff = NBIN - 1;
        for (int b = 0; b < 256; b++) {
            c2 += sh[b];
            if (c2 >= (unsigned)Ts) { cutoff = Gs * 256 + b; break; }
        }
        g_cutoff = (unsigned)cutoff;
    }
}

// ------------------ compact subset ------------------
__global__ void subsel_kernel()
{
    int i = blockIdx.x * 256 + threadIdx.x;
    if (i >= NBOX) return;
    ull k = g_keyU[i];
    if ((unsigned)(k >> 48) <= g_cutoff) {
        int pos = atomicAdd(&g_subCnt, 1);
        g_subKeyU[pos] = k;
    }
}

// ------------------ exact rank, scatter top-6000 ------------------
__global__ void rank_kernel()
{
    const int C = g_subCnt;
    if (blockIdx.x * 256 >= C) return;
    const int e = blockIdx.x * 256 + threadIdx.x;
    ull my = (e < C) ? g_subKeyU[e] : 0ULL;
    unsigned rank = 0;
    __shared__ ull tile[256];
    for (int t0 = 0; t0 < C; t0 += 256) {
        int idx = t0 + threadIdx.x;
        tile[threadIdx.x] = (idx < C) ? g_subKeyU[idx] : ~0ULL;
        __syncthreads();
        int lim = min(256, C - t0);
        if (e < C) {
#pragma unroll 4
            for (int q = 0; q < lim; q++)
                rank += (tile[q] < my);
        }
        __syncthreads();
    }
    if (e < C && rank < (unsigned)PRE) {
        g_sbox[rank] = g_roi[(unsigned)my];
        if ((unsigned)(my >> 32) < 0xFF800000u)
            atomicOr(&g_validBits[rank >> 5], 1u << (rank & 31));
    }
}

// ------------------ suppression bitmask ------------------
__global__ __launch_bounds__(256) void mask_kernel()
{
    const int jt = blockIdx.y;
    const int i  = blockIdx.x * 256 + threadIdx.x;
    __shared__ float4 jb[32];
    int j0 = jt * 32;
    if (threadIdx.x < 32) {
        int jj = j0 + threadIdx.x;
        jb[threadIdx.x] = (jj < PRE) ? g_sbox[jj] : make_float4(0.f, 0.f, 0.f, 0.f);
    }
    __syncthreads();
    if (i >= PRE) return;
    float4 bi = g_sbox[i];
    float areai = (bi.w - bi.y + 1.f) * (bi.z - bi.x + 1.f);
    unsigned word = 0u;
#pragma unroll 8
    for (int q = 0; q < 32; q++) {
        int j = j0 + q;
        if (j > i && j < PRE) {
            float4 bj = jb[q];
            float yy1 = fmaxf(bi.x, bj.x), xx1 = fmaxf(bi.y, bj.y);
            float yy2 = fminf(bi.z, bj.z), xx2 = fminf(bi.w, bj.w);
            float inter = fmaxf(0.f, xx2 - xx1 + 1.f) * fmaxf(0.f, yy2 - yy1 + 1.f);
            float areaj = (bj.w - bj.y + 1.f) * (bj.z - bj.x + 1.f);
            float iou = inter / (areai + areaj - inter);
            if (iou > 0.7f) word |= (1u << q);
        }
    }
    g_mask[(size_t)i * MASKW + jt] = word;
}

// ------------------ serial greedy NMS ------------------
__global__ void nms_kernel(float* __restrict__ out)
{
    const int lane = threadIdx.x;
    unsigned val[6], rem[6];
#pragma unroll
    for (int q = 0; q < 6; q++) {
        int w = 6 * lane + q;
        val[q] = (w < NW) ? g_validBits[w] : 0u;
        rem[q] = 0u;
    }
    for (int k = lane; k < POST * 4; k += 32) out[k] = 0.f;
    __syncwarp();

    for (int kept = 0; kept < POST; kept++) {
        int cand = 0x7FFFFFFF;
#pragma unroll
        for (int q = 0; q < 6; q++) {
            unsigned a = val[q] & ~rem[q];
            if (a && cand == 0x7FFFFFFF)
                cand = (6 * lane + q) * 32 + __ffs(a) - 1;
        }
        int i = __reduce_min_sync(0xFFFFFFFFu, cand);
        if (i == 0x7FFFFFFF) break;

        int ql = (i >> 5) - 6 * lane;
        if (ql >= 0 && ql < 6) rem[ql] |= (1u << (i & 31));

        if (lane == 0) {
            float4 bx = g_sbox[i];
            *(float4*)&out[kept * 4] = bx;
        }
        const uint2* row = (const uint2*)(g_mask + (size_t)i * MASKW);
        uint2 a0 = __ldg(&row[3 * lane]);
        uint2 a1 = __ldg(&row[3 * lane + 1]);
        uint2 a2 = __ldg(&row[3 * lane + 2]);
        rem[0] |= a0.x; rem[1] |= a0.y;
        rem[2] |= a1.x; rem[3] |= a1.y;
        rem[4] |= a2.x; rem[5] |= a2.y;
    }
}

// ------------------ launch ------------------
extern "C" void kernel_launch(void* const* d_in, const int* in_sizes, int n_in,
                              void* d_out, int out_size)
{
    const float* feat    = (const float*)d_in[0];
    const float* anchors = (const float*)d_in[1];
    const float* W1      = (const float*)d_in[2];
    const float* b1      = (const float*)d_in[3];
    const float* Wreg    = (const float*)d_in[4];
    const float* breg    = (const float*)d_in[5];
    const float* Wcls    = (const float*)d_in[6];
    const float* bcls    = (const float*)d_in[7];
    float* out = (float*)d_out;

    zero_kernel<<<(NBIN + 255) / 256, 256>>>();
    fold_kernel<<<dim3(144, 2), 192>>>(W1, Wreg, Wcls);
    sumw_kernel<<<(CIN * 9 * NOUT + 255) / 256, 256>>>();
    bias_kernel<<<1, 64>>>(Wreg, breg, Wcls, bcls, b1);
    main_kernel<<<dim3(16, 25), 160>>>(feat);
    decode_kernel<<<(NBOX + 255) / 256, 256>>>(anchors);
    gsum_kernel<<<256, 256>>>();
    binscan_kernel<<<1, 256>>>();
    subsel_kernel<<<(NBOX + 255) / 256, 256>>>();
    rank_kernel<<<(NBOX + 255) / 256, 256>>>();
    mask_kernel<<<dim3((PRE + 255) / 256, NW), 256>>>();
    nms_kernel<<<1, 32>>>(out);
}